// round 2
// baseline (speedup 1.0000x reference)
#include <cuda_runtime.h>
#include <cuda_bf16.h>
#include <cstdint>

// Problem constants
#define NB   8
#define NN   8192
#define CIN  64
#define COUT 128
#define KNB  16
#define MM   16
#define NPTS (NB*NN)            // 65536
#define AGGK (CIN*MM)           // 1024

// -------- device scratch (no allocations allowed) --------
__device__ float g_agg[(size_t)NPTS * AGGK];   // 268 MB, layout [p][m*64+c]
__device__ float g_Wp[(size_t)AGGK * COUT];    // permuted weight, row j = m*64+c
__device__ float g_A1[32*3];
__device__ float g_c1[32];

// ============================================================
// Prep 1: collapse MLP layer 1 (affine in rel coords).
// h1 = relu(W1 @ d_in + b1), d_in[e*16+m] = rel[e] - centers[e,m]
//   => h1 = relu(A1 @ rel + c1)
// ============================================================
__global__ void prep_kernel(const float* __restrict__ l1_w,
                            const float* __restrict__ l1_b,
                            const float* __restrict__ centers)
{
    int o = threadIdx.x;
    if (o >= 32) return;
    float a0 = 0.f, a1 = 0.f, a2 = 0.f;
    float c = l1_b[o];
    #pragma unroll
    for (int m = 0; m < MM; m++) {
        float w0 = l1_w[o*48 + 0*16 + m];
        float w1 = l1_w[o*48 + 1*16 + m];
        float w2 = l1_w[o*48 + 2*16 + m];
        a0 += w0; a1 += w1; a2 += w2;
        c -= w0 * centers[0*16 + m];
        c -= w1 * centers[1*16 + m];
        c -= w2 * centers[2*16 + m];
    }
    g_A1[o*3+0] = a0; g_A1[o*3+1] = a1; g_A1[o*3+2] = a2;
    g_c1[o] = c;
}

// ============================================================
// Prep 2: permute weight rows (c*16+m) -> (m*64+c) so kernel A's
// agg stores are coalesced while the GEMM stays a plain row-major GEMM.
// ============================================================
__global__ void permw_kernel(const float* __restrict__ weight)
{
    int e = blockIdx.x * blockDim.x + threadIdx.x;   // 0 .. 131071
    if (e >= AGGK * COUT) return;
    int j = e >> 7;        // permuted row, j = m*64 + c
    int o = e & 127;
    int c = j & 63;
    int m = j >> 6;
    g_Wp[e] = weight[((c*16 + m) << 7) + o];
}

// ============================================================
// Kernel A: gather + MLP + per-point agg.
// 1 warp = 1 output point; 8 warps (256 thr) per block; 8192 blocks.
//   lanes 0..15: neighbor k -> MLP -> D[k][0..15] in smem
//   all lanes:   gather F[16][64] into smem
//   all lanes:   agg[m*64+c] = sum_k F[k][c]*D[k][m], coalesced store
// ============================================================
__global__ __launch_bounds__(256)
void agg_kernel(const float* __restrict__ features,
                const float* __restrict__ input_pts,
                const float* __restrict__ output_pts,
                const int*   __restrict__ indices,
                const float* __restrict__ l2_w, const float* __restrict__ l2_b,
                const float* __restrict__ l3_w, const float* __restrict__ l3_b)
{
    __shared__ __align__(16) float sA1[96];
    __shared__ __align__(16) float sC1[32];
    __shared__ __align__(16) float sW2[16*32];
    __shared__ __align__(16) float sB2[16];
    __shared__ __align__(16) float sW3[16*16];
    __shared__ __align__(16) float sB3[16];
    __shared__ __align__(16) float sD[8][KNB][MM];     // 8 KB
    __shared__ __align__(16) float sF[8][KNB][CIN];    // 32 KB
    __shared__ int sIdx[8][KNB];

    const int tid = threadIdx.x;

    // stage MLP weights
    if (tid < 96)  sA1[tid] = g_A1[tid];
    if (tid < 32)  sC1[tid] = g_c1[tid];
    if (tid < 16)  { sB2[tid] = l2_b[tid]; sB3[tid] = l3_b[tid]; }
    for (int i = tid; i < 512; i += 256) sW2[i] = l2_w[i];
    sW3[tid] = l3_w[tid];                  // exactly 256 elements
    __syncthreads();

    const int w    = tid >> 5;
    const int lane = tid & 31;
    const int p    = blockIdx.x * 8 + w;   // 0 .. 65535
    const int b    = p >> 13;              // NN = 8192
    // no bounds check needed: grid exactly covers NPTS

    const float ox = output_pts[p*3+0];
    const float oy = output_pts[p*3+1];
    const float oz = output_pts[p*3+2];

    // ---- phase 1: MLP per neighbor (lanes 0..15) ----
    if (lane < KNB) {
        const int k   = lane;
        const int idx = indices[p*KNB + k];
        sIdx[w][k] = idx;
        const float* ip = input_pts + (size_t)(b*NN + idx) * 3;
        const float rx = ip[0] - ox, ry = ip[1] - oy, rz = ip[2] - oz;

        float h1[32];
        #pragma unroll
        for (int o = 0; o < 32; o++) {
            float v = sC1[o] + sA1[o*3+0]*rx + sA1[o*3+1]*ry + sA1[o*3+2]*rz;
            h1[o] = fmaxf(v, 0.f);
        }
        float h2[16];
        #pragma unroll
        for (int o = 0; o < 16; o++) {
            float v = sB2[o];
            #pragma unroll
            for (int i4 = 0; i4 < 8; i4++) {
                float4 wv = *(const float4*)&sW2[o*32 + i4*4];
                v += wv.x*h1[i4*4+0] + wv.y*h1[i4*4+1]
                   + wv.z*h1[i4*4+2] + wv.w*h1[i4*4+3];
            }
            h2[o] = fmaxf(v, 0.f);
        }
        #pragma unroll
        for (int o = 0; o < 16; o++) {
            float v = sB3[o];
            #pragma unroll
            for (int i4 = 0; i4 < 4; i4++) {
                float4 wv = *(const float4*)&sW3[o*16 + i4*4];
                v += wv.x*h2[i4*4+0] + wv.y*h2[i4*4+1]
                   + wv.z*h2[i4*4+2] + wv.w*h2[i4*4+3];
            }
            sD[w][k][o] = fmaxf(v, 0.f);
        }
    }
    __syncwarp();

    // ---- phase 2: gather neighbor features, 2 lanes per row ----
    {
        const int k = lane >> 1, half = lane & 1;
        const float4* src = (const float4*)(features
                            + (size_t)(b*NN + sIdx[w][k]) * CIN + half*32);
        float4* dst = (float4*)&sF[w][k][half*32];
        #pragma unroll
        for (int i = 0; i < 8; i++) dst[i] = src[i];
    }
    __syncwarp();

    // ---- phase 3: agg[c][m] = sum_k F[k][c] * D[k][m] ----
    float acc0[MM], acc1[MM];
    #pragma unroll
    for (int m = 0; m < MM; m++) { acc0[m] = 0.f; acc1[m] = 0.f; }
    const int c0 = lane, c1 = lane + 32;

    #pragma unroll
    for (int k = 0; k < KNB; k++) {
        const float f0 = sF[w][k][c0];
        const float f1 = sF[w][k][c1];
        #pragma unroll
        for (int m4 = 0; m4 < 4; m4++) {
            float4 d = *(const float4*)&sD[w][k][m4*4];
            acc0[m4*4+0] += f0 * d.x;  acc0[m4*4+1] += f0 * d.y;
            acc0[m4*4+2] += f0 * d.z;  acc0[m4*4+3] += f0 * d.w;
            acc1[m4*4+0] += f1 * d.x;  acc1[m4*4+1] += f1 * d.y;
            acc1[m4*4+2] += f1 * d.z;  acc1[m4*4+3] += f1 * d.w;
        }
    }

    // m-major layout -> each store coalesced across the warp
    float* orow = g_agg + (size_t)p * AGGK;
    #pragma unroll
    for (int m = 0; m < MM; m++) {
        orow[m*64 + c0] = acc0[m];
        orow[m*64 + c1] = acc1[m];
    }
}

// ============================================================
// Kernel B: SGEMM  out[65536,128] = (g_agg[65536,1024] @ g_Wp)/16 + bias
// 128x128x16 block tile, 256 threads, 8x8 microtile.
// ============================================================
#define BM 128
#define BN 128
#define BK 16
#define APAD 132   // padded As row to keep transposed STS ~conflict-free, 16B-aligned

__global__ __launch_bounds__(256)
void gemm_kernel(const float* __restrict__ bias, float* __restrict__ out)
{
    __shared__ __align__(16) float As[BK][APAD];
    __shared__ __align__(16) float Bs[BK][BN];

    const int tid = threadIdx.x;
    const int tx = tid & 15;        // 0..15 -> col group
    const int ty = tid >> 4;        // 0..15 -> row group
    const int p0 = blockIdx.x * BM;

    float acc[8][8];
    #pragma unroll
    for (int i = 0; i < 8; i++)
        #pragma unroll
        for (int j = 0; j < 8; j++) acc[i][j] = 0.f;

    for (int kc = 0; kc < AGGK; kc += BK) {
        // load A tile (128 rows x 16 k), store transposed As[k][row]
        #pragma unroll
        for (int h = 0; h < 2; h++) {
            int f   = tid + h*256;          // 0..511 float4s
            int row = f >> 2;
            int cg  = (f & 3) * 4;
            float4 v = *(const float4*)(g_agg + (size_t)(p0 + row)*AGGK + kc + cg);
            As[cg+0][row] = v.x;
            As[cg+1][row] = v.y;
            As[cg+2][row] = v.z;
            As[cg+3][row] = v.w;
        }
        // load B tile (16 k x 128 cols)
        #pragma unroll
        for (int h = 0; h < 2; h++) {
            int f   = tid + h*256;
            int row = f >> 5;
            int col = (f & 31) * 4;
            *(float4*)&Bs[row][col] =
                *(const float4*)(g_Wp + (size_t)(kc + row)*COUT + col);
        }
        __syncthreads();

        #pragma unroll
        for (int kk = 0; kk < BK; kk++) {
            float4 a0 = *(const float4*)&As[kk][ty*8];
            float4 a1 = *(const float4*)&As[kk][ty*8+4];
            float4 b0 = *(const float4*)&Bs[kk][tx*8];
            float4 b1 = *(const float4*)&Bs[kk][tx*8+4];
            float a[8] = {a0.x,a0.y,a0.z,a0.w,a1.x,a1.y,a1.z,a1.w};
            float bb[8] = {b0.x,b0.y,b0.z,b0.w,b1.x,b1.y,b1.z,b1.w};
            #pragma unroll
            for (int i = 0; i < 8; i++)
                #pragma unroll
                for (int j = 0; j < 8; j++)
                    acc[i][j] += a[i] * bb[j];
        }
        __syncthreads();
    }

    // epilogue: /K + bias
    const float inv_k = 1.0f / (float)KNB;
    float bv[8];
    #pragma unroll
    for (int j = 0; j < 8; j++) bv[j] = __ldg(&bias[tx*8 + j]);

    #pragma unroll
    for (int i = 0; i < 8; i++) {
        float* orow = out + (size_t)(p0 + ty*8 + i)*COUT + tx*8;
        float4 v0 = make_float4(acc[i][0]*inv_k + bv[0], acc[i][1]*inv_k + bv[1],
                                acc[i][2]*inv_k + bv[2], acc[i][3]*inv_k + bv[3]);
        float4 v1 = make_float4(acc[i][4]*inv_k + bv[4], acc[i][5]*inv_k + bv[5],
                                acc[i][6]*inv_k + bv[6], acc[i][7]*inv_k + bv[7]);
        *(float4*)(orow)     = v0;
        *(float4*)(orow + 4) = v1;
    }
}

// ============================================================
// Copy output_pts into the tail of the flattened tuple output.
// ============================================================
__global__ void copy_pts_kernel(const float* __restrict__ src, float* __restrict__ dst)
{
    int i = blockIdx.x * blockDim.x + threadIdx.x;   // float4 index
    const int n4 = (NPTS * 3) / 4;                   // 49152
    if (i < n4) ((float4*)dst)[i] = ((const float4*)src)[i];
}

// ============================================================
extern "C" void kernel_launch(void* const* d_in, const int* in_sizes, int n_in,
                              void* d_out, int out_size)
{
    const float* features   = (const float*)d_in[0];
    const float* input_pts  = (const float*)d_in[1];
    const float* output_pts = (const float*)d_in[2];
    const int*   indices    = (const int*)  d_in[3];
    const float* centers    = (const float*)d_in[4];
    const float* weight     = (const float*)d_in[5];
    const float* bias       = (const float*)d_in[6];
    const float* l1_w       = (const float*)d_in[7];
    const float* l1_b       = (const float*)d_in[8];
    const float* l2_w       = (const float*)d_in[9];
    const float* l2_b       = (const float*)d_in[10];
    const float* l3_w       = (const float*)d_in[11];
    const float* l3_b       = (const float*)d_in[12];

    float* out = (float*)d_out;

    prep_kernel<<<1, 32>>>(l1_w, l1_b, centers);
    permw_kernel<<<(AGGK*COUT + 255)/256, 256>>>(weight);
    agg_kernel<<<NPTS/8, 256>>>(features, input_pts, output_pts, indices,
                                l2_w, l2_b, l3_w, l3_b);
    gemm_kernel<<<NPTS/BM, 256>>>(bias, out);

    // tuple tail: output_pts passthrough
    if (out_size >= NPTS*COUT + NPTS*3) {
        copy_pts_kernel<<<(NPTS*3/4 + 255)/256, 256>>>(output_pts, out + (size_t)NPTS*COUT);
    }
}

// round 4
// speedup vs baseline: 1.7636x; 1.7636x over previous
#include <cuda_runtime.h>
#include <cuda_bf16.h>
#include <cstdint>

// Problem constants
#define NB   8
#define NN   8192
#define CIN  64
#define COUT 128
#define KNB  16
#define MM   16
#define NPTS (NB*NN)            // 65536
#define AGGK (CIN*MM)           // 1024

// -------- device scratch (no allocations allowed) --------
__device__ float g_agg[(size_t)NPTS * AGGK];   // 268 MB, [p][j], j=m*64+c, tf32-rounded
__device__ float g_WpT[(size_t)COUT * AGGK];   // weight^T, [n][j] K-major, tf32-rounded
__device__ float g_A1[32*3];
__device__ float g_c1[32];

// ============================================================
// Small PTX helpers (generic-target-safe only: cp.async + mma.sync)
// ============================================================
__device__ __forceinline__ uint32_t smem_u32(const void* p) {
    uint32_t a;
    asm("{ .reg .u64 t; cvta.to.shared.u64 t, %1; cvt.u32.u64 %0, t; }" : "=r"(a) : "l"(p));
    return a;
}
__device__ __forceinline__ float to_tf32(float x) {
    uint32_t u;
    asm("cvt.rna.tf32.f32 %0, %1;" : "=r"(u) : "f"(x));
    return __uint_as_float(u);
}
#define CP_ASYNC16(dst, src) \
    asm volatile("cp.async.cg.shared.global [%0], [%1], 16;" :: "r"(dst), "l"(src) : "memory")
#define CP_COMMIT() asm volatile("cp.async.commit_group;" ::: "memory")
#define CP_WAIT1()  asm volatile("cp.async.wait_group 1;" ::: "memory")
#define CP_WAIT0()  asm volatile("cp.async.wait_group 0;" ::: "memory")

__device__ __forceinline__ void mma_tf32(float c[4], const uint32_t a[4], const uint32_t b[2]) {
    asm volatile(
        "mma.sync.aligned.m16n8k8.row.col.f32.tf32.tf32.f32 "
        "{%0,%1,%2,%3}, {%4,%5,%6,%7}, {%8,%9}, {%0,%1,%2,%3};"
        : "+f"(c[0]), "+f"(c[1]), "+f"(c[2]), "+f"(c[3])
        : "r"(a[0]), "r"(a[1]), "r"(a[2]), "r"(a[3]), "r"(b[0]), "r"(b[1]));
}

// ============================================================
// Prep 1: collapse MLP layer 1 (affine in rel coords).
// ============================================================
__global__ void prep_kernel(const float* __restrict__ l1_w,
                            const float* __restrict__ l1_b,
                            const float* __restrict__ centers)
{
    int o = threadIdx.x;
    if (o >= 32) return;
    float a0 = 0.f, a1 = 0.f, a2 = 0.f;
    float c = l1_b[o];
    #pragma unroll
    for (int m = 0; m < MM; m++) {
        float w0 = l1_w[o*48 + 0*16 + m];
        float w1 = l1_w[o*48 + 1*16 + m];
        float w2 = l1_w[o*48 + 2*16 + m];
        a0 += w0; a1 += w1; a2 += w2;
        c -= w0 * centers[0*16 + m];
        c -= w1 * centers[1*16 + m];
        c -= w2 * centers[2*16 + m];
    }
    g_A1[o*3+0] = a0; g_A1[o*3+1] = a1; g_A1[o*3+2] = a2;
    g_c1[o] = c;
}

// ============================================================
// Prep 2: weight[(c*16+m)*128 + n] -> g_WpT[n*1024 + (m*64+c)], tf32-rounded
// ============================================================
__global__ void permw_kernel(const float* __restrict__ weight)
{
    int e = blockIdx.x * blockDim.x + threadIdx.x;
    if (e >= AGGK * COUT) return;
    int j = e & 1023;
    int n = e >> 10;
    int c = j & 63;
    int m = j >> 6;
    g_WpT[e] = to_tf32(weight[((c*16 + m) << 7) + n]);
}

// ============================================================
// Kernel A: gather + MLP + per-point agg (tf32-rounded stores).
// ============================================================
__global__ __launch_bounds__(256)
void agg_kernel(const float* __restrict__ features,
                const float* __restrict__ input_pts,
                const float* __restrict__ output_pts,
                const int*   __restrict__ indices,
                const float* __restrict__ l2_w, const float* __restrict__ l2_b,
                const float* __restrict__ l3_w, const float* __restrict__ l3_b)
{
    __shared__ __align__(16) float sA1[96];
    __shared__ __align__(16) float sC1[32];
    __shared__ __align__(16) float sW2[16*32];
    __shared__ __align__(16) float sB2[16];
    __shared__ __align__(16) float sW3[16*16];
    __shared__ __align__(16) float sB3[16];
    __shared__ __align__(16) float sD[8][KNB][MM];
    __shared__ __align__(16) float sF[8][KNB][CIN];
    __shared__ int sIdx[8][KNB];

    const int tid = threadIdx.x;

    if (tid < 96)  sA1[tid] = g_A1[tid];
    if (tid < 32)  sC1[tid] = g_c1[tid];
    if (tid < 16)  { sB2[tid] = l2_b[tid]; sB3[tid] = l3_b[tid]; }
    for (int i = tid; i < 512; i += 256) sW2[i] = l2_w[i];
    sW3[tid] = l3_w[tid];
    __syncthreads();

    const int w    = tid >> 5;
    const int lane = tid & 31;
    const int p    = blockIdx.x * 8 + w;
    const int b    = p >> 13;

    const float ox = output_pts[p*3+0];
    const float oy = output_pts[p*3+1];
    const float oz = output_pts[p*3+2];

    if (lane < KNB) {
        const int k   = lane;
        const int idx = indices[p*KNB + k];
        sIdx[w][k] = idx;
        const float* ip = input_pts + (size_t)(b*NN + idx) * 3;
        const float rx = ip[0] - ox, ry = ip[1] - oy, rz = ip[2] - oz;

        float h1[32];
        #pragma unroll
        for (int o = 0; o < 32; o++) {
            float v = sC1[o] + sA1[o*3+0]*rx + sA1[o*3+1]*ry + sA1[o*3+2]*rz;
            h1[o] = fmaxf(v, 0.f);
        }
        float h2[16];
        #pragma unroll
        for (int o = 0; o < 16; o++) {
            float v = sB2[o];
            #pragma unroll
            for (int i4 = 0; i4 < 8; i4++) {
                float4 wv = *(const float4*)&sW2[o*32 + i4*4];
                v += wv.x*h1[i4*4+0] + wv.y*h1[i4*4+1]
                   + wv.z*h1[i4*4+2] + wv.w*h1[i4*4+3];
            }
            h2[o] = fmaxf(v, 0.f);
        }
        #pragma unroll
        for (int o = 0; o < 16; o++) {
            float v = sB3[o];
            #pragma unroll
            for (int i4 = 0; i4 < 4; i4++) {
                float4 wv = *(const float4*)&sW3[o*16 + i4*4];
                v += wv.x*h2[i4*4+0] + wv.y*h2[i4*4+1]
                   + wv.z*h2[i4*4+2] + wv.w*h2[i4*4+3];
            }
            sD[w][k][o] = fmaxf(v, 0.f);
        }
    }
    __syncwarp();

    {
        const int k = lane >> 1, half = lane & 1;
        const float4* src = (const float4*)(features
                            + (size_t)(b*NN + sIdx[w][k]) * CIN + half*32);
        float4* dst = (float4*)&sF[w][k][half*32];
        #pragma unroll
        for (int i = 0; i < 8; i++) dst[i] = src[i];
    }
    __syncwarp();

    float acc0[MM], acc1[MM];
    #pragma unroll
    for (int m = 0; m < MM; m++) { acc0[m] = 0.f; acc1[m] = 0.f; }
    const int c0 = lane, c1 = lane + 32;

    #pragma unroll
    for (int k = 0; k < KNB; k++) {
        const float f0 = sF[w][k][c0];
        const float f1 = sF[w][k][c1];
        #pragma unroll
        for (int m4 = 0; m4 < 4; m4++) {
            float4 d = *(const float4*)&sD[w][k][m4*4];
            acc0[m4*4+0] += f0 * d.x;  acc0[m4*4+1] += f0 * d.y;
            acc0[m4*4+2] += f0 * d.z;  acc0[m4*4+3] += f0 * d.w;
            acc1[m4*4+0] += f1 * d.x;  acc1[m4*4+1] += f1 * d.y;
            acc1[m4*4+2] += f1 * d.z;  acc1[m4*4+3] += f1 * d.w;
        }
    }

    float* orow = g_agg + (size_t)p * AGGK;
    #pragma unroll
    for (int m = 0; m < MM; m++) {
        orow[m*64 + c0] = to_tf32(acc0[m]);
        orow[m*64 + c1] = to_tf32(acc1[m]);
    }
}

// ============================================================
// Kernel B: tf32 mma.sync GEMM (generic-target HMMA path).
// out[65536,128] = (g_agg[65536,1024] @ g_WpT^T)/16 + bias
// 128x128x32 CTA tile, 256 thr, 8 warps (2x4), warp tile 64x32,
// double-buffered cp.async, pitch-36 smem => conflict-free frag loads.
// ============================================================
#define GBM 128
#define GBN 128
#define GBK 32
#define PITCH 36                      // bank(frag) = g*4 + t4, all 32 distinct
#define TSZB  (GBM * PITCH * 4)       // 18432 B per tile per stage
#define GEMM_SMEM (4*TSZB + 512)      // A0 A1 B0 B1 + bias

__global__ __launch_bounds__(256)
void gemm_mma_kernel(const float* __restrict__ bias, float* __restrict__ out)
{
    extern __shared__ __align__(16) char smem[];
    float* sbias = (float*)(smem + 4*TSZB);

    const int tid  = threadIdx.x;
    const int lane = tid & 31;
    const int warp = tid >> 5;
    const int g    = lane >> 2;       // groupID 0..7
    const int t4   = lane & 3;        // threadID_in_group
    const int m0   = (warp >> 2) * 64;
    const int n0   = (warp & 3) * 32;
    const int p0   = blockIdx.x * GBM;

    if (tid < COUT) sbias[tid] = bias[tid];

    // cp.async source/dest for this thread: 4 rows apart by 32
    const int ldr = tid >> 3;                 // 0..31 base row
    const int lc4 = (tid & 7) * 4;            // float offset within 32-float chunk
    const float* srcA = g_agg + (size_t)(p0 + ldr) * AGGK + lc4;
    const float* srcB = g_WpT + (size_t)ldr * AGGK + lc4;
    const uint32_t smb = smem_u32(smem);
    const uint32_t dstA = smb + ldr*(PITCH*4) + (tid & 7)*16;
    const uint32_t dstB = smb + 2*TSZB + ldr*(PITCH*4) + (tid & 7)*16;

    auto load_chunk = [&](int kc, int st) {
        const float* a = srcA + kc*GBK;
        const float* b = srcB + kc*GBK;
        const uint32_t da = dstA + st*TSZB;
        const uint32_t db = dstB + st*TSZB;
        #pragma unroll
        for (int i = 0; i < 4; i++) {
            CP_ASYNC16(da + i*32*(PITCH*4), a + (size_t)i*32*AGGK);
            CP_ASYNC16(db + i*32*(PITCH*4), b + (size_t)i*32*AGGK);
        }
    };

    float c[4][4][4];
    #pragma unroll
    for (int mf = 0; mf < 4; mf++)
        #pragma unroll
        for (int nf = 0; nf < 4; nf++)
            #pragma unroll
            for (int i = 0; i < 4; i++) c[mf][nf][i] = 0.f;

    load_chunk(0, 0);
    CP_COMMIT();

    int s = 0;
    const int NCH = AGGK / GBK;      // 32
    for (int kc = 0; kc < NCH; kc++) {
        if (kc + 1 < NCH) {
            load_chunk(kc + 1, s ^ 1);
            CP_COMMIT();
            CP_WAIT1();
        } else {
            CP_WAIT0();
        }
        __syncthreads();

        const uint32_t* As = (const uint32_t*)(smem + s*TSZB);
        const uint32_t* Bs = (const uint32_t*)(smem + 2*TSZB + s*TSZB);

        #pragma unroll
        for (int kk = 0; kk < 4; kk++) {
            const int k0 = kk * 8;
            uint32_t a[4][4], bfr[4][2];
            #pragma unroll
            for (int mf = 0; mf < 4; mf++) {
                const uint32_t* ap = As + (m0 + mf*16 + g)*PITCH + k0 + t4;
                a[mf][0] = ap[0];
                a[mf][1] = ap[8*PITCH];
                a[mf][2] = ap[4];
                a[mf][3] = ap[8*PITCH + 4];
            }
            #pragma unroll
            for (int nf = 0; nf < 4; nf++) {
                const uint32_t* bp = Bs + (n0 + nf*8 + g)*PITCH + k0 + t4;
                bfr[nf][0] = bp[0];
                bfr[nf][1] = bp[4];
            }
            #pragma unroll
            for (int mf = 0; mf < 4; mf++)
                #pragma unroll
                for (int nf = 0; nf < 4; nf++)
                    mma_tf32(c[mf][nf], a[mf], bfr[nf]);
        }
        __syncthreads();
        s ^= 1;
    }

    // epilogue: /K + bias, float2 stores (full 32B sectors per row-group)
    const float inv_k = 1.0f / (float)KNB;
    #pragma unroll
    for (int mf = 0; mf < 4; mf++) {
        const int row = p0 + m0 + mf*16 + g;
        #pragma unroll
        for (int nf = 0; nf < 4; nf++) {
            const int col = n0 + nf*8 + t4*2;
            const float b0 = sbias[col], b1 = sbias[col+1];
            float2 v0 = make_float2(c[mf][nf][0]*inv_k + b0, c[mf][nf][1]*inv_k + b1);
            float2 v1 = make_float2(c[mf][nf][2]*inv_k + b0, c[mf][nf][3]*inv_k + b1);
            *(float2*)(out + (size_t)row*COUT + col)       = v0;
            *(float2*)(out + (size_t)(row+8)*COUT + col)   = v1;
        }
    }
}

// ============================================================
// Copy output_pts into the tail of the flattened tuple output.
// ============================================================
__global__ void copy_pts_kernel(const float* __restrict__ src, float* __restrict__ dst)
{
    int i = blockIdx.x * blockDim.x + threadIdx.x;
    const int n4 = (NPTS * 3) / 4;
    if (i < n4) ((float4*)dst)[i] = ((const float4*)src)[i];
}

// ============================================================
extern "C" void kernel_launch(void* const* d_in, const int* in_sizes, int n_in,
                              void* d_out, int out_size)
{
    const float* features   = (const float*)d_in[0];
    const float* input_pts  = (const float*)d_in[1];
    const float* output_pts = (const float*)d_in[2];
    const int*   indices    = (const int*)  d_in[3];
    const float* centers    = (const float*)d_in[4];
    const float* weight     = (const float*)d_in[5];
    const float* bias       = (const float*)d_in[6];
    const float* l1_w       = (const float*)d_in[7];
    const float* l1_b       = (const float*)d_in[8];
    const float* l2_w       = (const float*)d_in[9];
    const float* l2_b       = (const float*)d_in[10];
    const float* l3_w       = (const float*)d_in[11];
    const float* l3_b       = (const float*)d_in[12];

    float* out = (float*)d_out;

    cudaFuncSetAttribute(gemm_mma_kernel,
                         cudaFuncAttributeMaxDynamicSharedMemorySize, GEMM_SMEM);

    prep_kernel<<<1, 32>>>(l1_w, l1_b, centers);
    permw_kernel<<<(AGGK*COUT + 255)/256, 256>>>(weight);
    agg_kernel<<<NPTS/8, 256>>>(features, input_pts, output_pts, indices,
                                l2_w, l2_b, l3_w, l3_b);
    gemm_mma_kernel<<<NPTS/GBM, 256, GEMM_SMEM>>>(bias, out);

    if (out_size >= NPTS*COUT + NPTS*3) {
        copy_pts_kernel<<<(NPTS*3/4 + 255)/256, 256>>>(output_pts, out + (size_t)NPTS*COUT);
    }
}

// round 5
// speedup vs baseline: 2.7014x; 1.5317x over previous
#include <cuda_runtime.h>
#include <cuda_bf16.h>
#include <cstdint>

// Problem constants
#define NB   8
#define NN   8192
#define CIN  64
#define COUT 128
#define KNB  16
#define MM   16
#define NPTS (NB*NN)            // 65536
#define AGGK (CIN*MM)           // 1024

// -------- device scratch (no allocations allowed) --------
__device__ float g_agg[(size_t)NPTS * AGGK];   // 268 MB, [p][j], j=m*64+c, tf32-rounded
__device__ float g_WpT[(size_t)COUT * AGGK];   // weight^T, [n][j] K-major, tf32-rounded
__device__ float g_A1[32*3];
__device__ float g_c1[32];

// ============================================================
// Small PTX helpers (generic-target-safe only: cp.async + mma.sync)
// ============================================================
__device__ __forceinline__ uint32_t smem_u32(const void* p) {
    uint32_t a;
    asm("{ .reg .u64 t; cvta.to.shared.u64 t, %1; cvt.u32.u64 %0, t; }" : "=r"(a) : "l"(p));
    return a;
}
__device__ __forceinline__ float to_tf32(float x) {
    uint32_t u;
    asm("cvt.rna.tf32.f32 %0, %1;" : "=r"(u) : "f"(x));
    return __uint_as_float(u);
}
__device__ __forceinline__ uint32_t to_tf32u(float x) {
    uint32_t u;
    asm("cvt.rna.tf32.f32 %0, %1;" : "=r"(u) : "f"(x));
    return u;
}
#define CP_ASYNC16(dst, src) \
    asm volatile("cp.async.cg.shared.global [%0], [%1], 16;" :: "r"(dst), "l"(src) : "memory")
#define CP_COMMIT() asm volatile("cp.async.commit_group;" ::: "memory")
#define CP_WAIT1()  asm volatile("cp.async.wait_group 1;" ::: "memory")
#define CP_WAIT0()  asm volatile("cp.async.wait_group 0;" ::: "memory")

__device__ __forceinline__ void mma_tf32(float c[4], const uint32_t a[4], const uint32_t b[2]) {
    asm volatile(
        "mma.sync.aligned.m16n8k8.row.col.f32.tf32.tf32.f32 "
        "{%0,%1,%2,%3}, {%4,%5,%6,%7}, {%8,%9}, {%0,%1,%2,%3};"
        : "+f"(c[0]), "+f"(c[1]), "+f"(c[2]), "+f"(c[3])
        : "r"(a[0]), "r"(a[1]), "r"(a[2]), "r"(a[3]), "r"(b[0]), "r"(b[1]));
}

// ============================================================
// Prep 1: collapse MLP layer 1 (affine in rel coords).
// ============================================================
__global__ void prep_kernel(const float* __restrict__ l1_w,
                            const float* __restrict__ l1_b,
                            const float* __restrict__ centers)
{
    int o = threadIdx.x;
    if (o >= 32) return;
    float a0 = 0.f, a1 = 0.f, a2 = 0.f;
    float c = l1_b[o];
    #pragma unroll
    for (int m = 0; m < MM; m++) {
        float w0 = l1_w[o*48 + 0*16 + m];
        float w1 = l1_w[o*48 + 1*16 + m];
        float w2 = l1_w[o*48 + 2*16 + m];
        a0 += w0; a1 += w1; a2 += w2;
        c -= w0 * centers[0*16 + m];
        c -= w1 * centers[1*16 + m];
        c -= w2 * centers[2*16 + m];
    }
    g_A1[o*3+0] = a0; g_A1[o*3+1] = a1; g_A1[o*3+2] = a2;
    g_c1[o] = c;
}

// ============================================================
// Prep 2: weight[(c*16+m)*128 + n] -> g_WpT[n*1024 + (m*64+c)], tf32-rounded
// ============================================================
__global__ void permw_kernel(const float* __restrict__ weight)
{
    int e = blockIdx.x * blockDim.x + threadIdx.x;
    if (e >= AGGK * COUT) return;
    int j = e & 1023;
    int n = e >> 10;
    int c = j & 63;
    int m = j >> 6;
    g_WpT[e] = to_tf32(weight[((c*16 + m) << 7) + n]);
}

// ============================================================
// Kernel A (v2): gather + MLP + per-point agg via mma.sync.
// 1 warp = 2 points. MLP: lane = (q = lane>>4, k = lane&15), all lanes busy.
// Phase 3 per point: S[64c,16m] = F^T @ D with 16x m16n8k8 tf32 MMAs;
// A-fragments gathered directly from global at fragment positions.
// Block = 128 threads (4 warps, 8 points). Grid = NPTS/8.
// ============================================================
#define DP 17   // sD row pitch (conflict-free STS)

__global__ __launch_bounds__(128)
void agg_kernel(const float* __restrict__ features,
                const float* __restrict__ input_pts,
                const float* __restrict__ output_pts,
                const int*   __restrict__ indices,
                const float* __restrict__ l2_w, const float* __restrict__ l2_b,
                const float* __restrict__ l3_w, const float* __restrict__ l3_b)
{
    __shared__ __align__(16) float sA1[96];
    __shared__ __align__(16) float sC1[32];
    __shared__ __align__(16) float sW2[16*32];
    __shared__ __align__(16) float sB2[16];
    __shared__ __align__(16) float sW3[16*16];
    __shared__ __align__(16) float sB3[16];
    __shared__ float sD[4][32][DP];       // [warp][q*16+k][m], pitch 17
    __shared__ int   sI[4][2][KNB];

    const int tid = threadIdx.x;

    if (tid < 96)  sA1[tid] = g_A1[tid];
    if (tid < 32)  sC1[tid] = g_c1[tid];
    if (tid < 16)  { sB2[tid] = l2_b[tid]; sB3[tid] = l3_b[tid]; }
    for (int i = tid; i < 512; i += 128) sW2[i] = l2_w[i];
    for (int i = tid; i < 256; i += 128) sW3[i] = l3_w[i];
    __syncthreads();

    const int w     = tid >> 5;
    const int lane  = tid & 31;
    const int g     = lane >> 2;          // 0..7
    const int t4    = lane & 3;           // 0..3
    const int q     = lane >> 4;          // 0/1 (MLP half)
    const int k     = lane & 15;          // neighbor (MLP)
    const int pbase = blockIdx.x * 8 + w * 2;
    const int b     = pbase >> 13;        // pbase, pbase+1 same batch (NN even)
    const float* __restrict__ fb = features + (size_t)b * NN * CIN;

    // ---- phase 1: MLP, all 32 lanes (point q, neighbor k) ----
    {
        const int p   = pbase + q;
        const int idx = indices[p*KNB + k];
        sI[w][q][k] = idx;
        const float ox = output_pts[p*3+0];
        const float oy = output_pts[p*3+1];
        const float oz = output_pts[p*3+2];
        const float* ip = input_pts + (size_t)(b*NN + idx) * 3;
        const float rx = ip[0] - ox, ry = ip[1] - oy, rz = ip[2] - oz;

        float h1[32];
        #pragma unroll
        for (int o = 0; o < 32; o++) {
            float v = sC1[o] + sA1[o*3+0]*rx + sA1[o*3+1]*ry + sA1[o*3+2]*rz;
            h1[o] = fmaxf(v, 0.f);
        }
        float h2[16];
        #pragma unroll
        for (int o = 0; o < 16; o++) {
            float v = sB2[o];
            #pragma unroll
            for (int i4 = 0; i4 < 8; i4++) {
                float4 wv = *(const float4*)&sW2[o*32 + i4*4];
                v += wv.x*h1[i4*4+0] + wv.y*h1[i4*4+1]
                   + wv.z*h1[i4*4+2] + wv.w*h1[i4*4+3];
            }
            h2[o] = fmaxf(v, 0.f);
        }
        float* drow = sD[w][q*16 + k];
        #pragma unroll
        for (int o = 0; o < 16; o++) {
            float v = sB3[o];
            #pragma unroll
            for (int i4 = 0; i4 < 4; i4++) {
                float4 wv = *(const float4*)&sW3[o*16 + i4*4];
                v += wv.x*h2[i4*4+0] + wv.y*h2[i4*4+1]
                   + wv.z*h2[i4*4+2] + wv.w*h2[i4*4+3];
            }
            drow[o] = fmaxf(v, 0.f);
        }
    }
    __syncwarp();

    // ---- phase 3: per point, S = F^T(64x16) @ D(16x16) on tensor cores ----
    #pragma unroll
    for (int qq = 0; qq < 2; qq++) {
        float acc[4][2][4];
        #pragma unroll
        for (int mt = 0; mt < 4; mt++)
            #pragma unroll
            for (int nt = 0; nt < 2; nt++)
                #pragma unroll
                for (int i = 0; i < 4; i++) acc[mt][nt][i] = 0.f;

        #pragma unroll
        for (int kc = 0; kc < 2; kc++) {
            // row pointers for this lane's fragment k indices
            const float* r0 = fb + (size_t)sI[w][qq][kc*8 + t4]     * CIN;
            const float* r1 = fb + (size_t)sI[w][qq][kc*8 + t4 + 4] * CIN;

            // B fragments from sD: b0 = D[kc*8+t4][nt*8+g], b1 = D[+4][...]
            uint32_t bfr[2][2];
            #pragma unroll
            for (int nt = 0; nt < 2; nt++) {
                bfr[nt][0] = to_tf32u(sD[w][qq*16 + kc*8 + t4    ][nt*8 + g]);
                bfr[nt][1] = to_tf32u(sD[w][qq*16 + kc*8 + t4 + 4][nt*8 + g]);
            }

            // A fragments straight from global (F[k][c] at fragment position)
            uint32_t a[4][4];
            #pragma unroll
            for (int mt = 0; mt < 4; mt++) {
                a[mt][0] = to_tf32u(r0[mt*16 + g    ]);
                a[mt][1] = to_tf32u(r0[mt*16 + g + 8]);
                a[mt][2] = to_tf32u(r1[mt*16 + g    ]);
                a[mt][3] = to_tf32u(r1[mt*16 + g + 8]);
            }

            #pragma unroll
            for (int mt = 0; mt < 4; mt++) {
                mma_tf32(acc[mt][0], a[mt], bfr[0]);
                mma_tf32(acc[mt][1], a[mt], bfr[1]);
            }
        }

        // store: S[c_ch = mt*16+g(+8)][m_k = nt*8+t4*2(+1)] -> g_agg[m_k*64+c_ch]
        float* orow = g_agg + (size_t)(pbase + qq) * AGGK;
        #pragma unroll
        for (int mt = 0; mt < 4; mt++) {
            #pragma unroll
            for (int nt = 0; nt < 2; nt++) {
                const int col = nt*8 + t4*2;
                const int row = mt*16 + g;
                orow[ col   *64 + row    ] = to_tf32(acc[mt][nt][0]);
                orow[(col+1)*64 + row    ] = to_tf32(acc[mt][nt][1]);
                orow[ col   *64 + row + 8] = to_tf32(acc[mt][nt][2]);
                orow[(col+1)*64 + row + 8] = to_tf32(acc[mt][nt][3]);
            }
        }
    }
}

// ============================================================
// Kernel B: tf32 mma.sync GEMM (unchanged from R4, 127.5us).
// ============================================================
#define GBM 128
#define GBN 128
#define GBK 32
#define PITCH 36
#define TSZB  (GBM * PITCH * 4)
#define GEMM_SMEM (4*TSZB + 512)

__global__ __launch_bounds__(256)
void gemm_mma_kernel(const float* __restrict__ bias, float* __restrict__ out)
{
    extern __shared__ __align__(16) char smem[];
    float* sbias = (float*)(smem + 4*TSZB);

    const int tid  = threadIdx.x;
    const int lane = tid & 31;
    const int warp = tid >> 5;
    const int g    = lane >> 2;
    const int t4   = lane & 3;
    const int m0   = (warp >> 2) * 64;
    const int n0   = (warp & 3) * 32;
    const int p0   = blockIdx.x * GBM;

    if (tid < COUT) sbias[tid] = bias[tid];

    const int ldr = tid >> 3;
    const int lc4 = (tid & 7) * 4;
    const float* srcA = g_agg + (size_t)(p0 + ldr) * AGGK + lc4;
    const float* srcB = g_WpT + (size_t)ldr * AGGK + lc4;
    const uint32_t smb = smem_u32(smem);
    const uint32_t dstA = smb + ldr*(PITCH*4) + (tid & 7)*16;
    const uint32_t dstB = smb + 2*TSZB + ldr*(PITCH*4) + (tid & 7)*16;

    auto load_chunk = [&](int kc, int st) {
        const float* a = srcA + kc*GBK;
        const float* b = srcB + kc*GBK;
        const uint32_t da = dstA + st*TSZB;
        const uint32_t db = dstB + st*TSZB;
        #pragma unroll
        for (int i = 0; i < 4; i++) {
            CP_ASYNC16(da + i*32*(PITCH*4), a + (size_t)i*32*AGGK);
            CP_ASYNC16(db + i*32*(PITCH*4), b + (size_t)i*32*AGGK);
        }
    };

    float c[4][4][4];
    #pragma unroll
    for (int mf = 0; mf < 4; mf++)
        #pragma unroll
        for (int nf = 0; nf < 4; nf++)
            #pragma unroll
            for (int i = 0; i < 4; i++) c[mf][nf][i] = 0.f;

    load_chunk(0, 0);
    CP_COMMIT();

    int s = 0;
    const int NCH = AGGK / GBK;
    for (int kc = 0; kc < NCH; kc++) {
        if (kc + 1 < NCH) {
            load_chunk(kc + 1, s ^ 1);
            CP_COMMIT();
            CP_WAIT1();
        } else {
            CP_WAIT0();
        }
        __syncthreads();

        const uint32_t* As = (const uint32_t*)(smem + s*TSZB);
        const uint32_t* Bs = (const uint32_t*)(smem + 2*TSZB + s*TSZB);

        #pragma unroll
        for (int kk = 0; kk < 4; kk++) {
            const int k0 = kk * 8;
            uint32_t a[4][4], bfr[4][2];
            #pragma unroll
            for (int mf = 0; mf < 4; mf++) {
                const uint32_t* ap = As + (m0 + mf*16 + g)*PITCH + k0 + t4;
                a[mf][0] = ap[0];
                a[mf][1] = ap[8*PITCH];
                a[mf][2] = ap[4];
                a[mf][3] = ap[8*PITCH + 4];
            }
            #pragma unroll
            for (int nf = 0; nf < 4; nf++) {
                const uint32_t* bp = Bs + (n0 + nf*8 + g)*PITCH + k0 + t4;
                bfr[nf][0] = bp[0];
                bfr[nf][1] = bp[4];
            }
            #pragma unroll
            for (int mf = 0; mf < 4; mf++)
                #pragma unroll
                for (int nf = 0; nf < 4; nf++)
                    mma_tf32(c[mf][nf], a[mf], bfr[nf]);
        }
        __syncthreads();
        s ^= 1;
    }

    const float inv_k = 1.0f / (float)KNB;
    #pragma unroll
    for (int mf = 0; mf < 4; mf++) {
        const int row = p0 + m0 + mf*16 + g;
        #pragma unroll
        for (int nf = 0; nf < 4; nf++) {
            const int col = n0 + nf*8 + t4*2;
            const float b0 = sbias[col], b1 = sbias[col+1];
            float2 v0 = make_float2(c[mf][nf][0]*inv_k + b0, c[mf][nf][1]*inv_k + b1);
            float2 v1 = make_float2(c[mf][nf][2]*inv_k + b0, c[mf][nf][3]*inv_k + b1);
            *(float2*)(out + (size_t)row*COUT + col)       = v0;
            *(float2*)(out + (size_t)(row+8)*COUT + col)   = v1;
        }
    }
}

// ============================================================
// Copy output_pts into the tail of the flattened tuple output.
// ============================================================
__global__ void copy_pts_kernel(const float* __restrict__ src, float* __restrict__ dst)
{
    int i = blockIdx.x * blockDim.x + threadIdx.x;
    const int n4 = (NPTS * 3) / 4;
    if (i < n4) ((float4*)dst)[i] = ((const float4*)src)[i];
}

// ============================================================
extern "C" void kernel_launch(void* const* d_in, const int* in_sizes, int n_in,
                              void* d_out, int out_size)
{
    const float* features   = (const float*)d_in[0];
    const float* input_pts  = (const float*)d_in[1];
    const float* output_pts = (const float*)d_in[2];
    const int*   indices    = (const int*)  d_in[3];
    const float* centers    = (const float*)d_in[4];
    const float* weight     = (const float*)d_in[5];
    const float* bias       = (const float*)d_in[6];
    const float* l1_w       = (const float*)d_in[7];
    const float* l1_b       = (const float*)d_in[8];
    const float* l2_w       = (const float*)d_in[9];
    const float* l2_b       = (const float*)d_in[10];
    const float* l3_w       = (const float*)d_in[11];
    const float* l3_b       = (const float*)d_in[12];

    float* out = (float*)d_out;

    cudaFuncSetAttribute(gemm_mma_kernel,
                         cudaFuncAttributeMaxDynamicSharedMemorySize, GEMM_SMEM);

    prep_kernel<<<1, 32>>>(l1_w, l1_b, centers);
    permw_kernel<<<(AGGK*COUT + 255)/256, 256>>>(weight);
    agg_kernel<<<NPTS/8, 128>>>(features, input_pts, output_pts, indices,
                                l2_w, l2_b, l3_w, l3_b);
    gemm_mma_kernel<<<NPTS/GBM, 256, GEMM_SMEM>>>(bias, out);

    if (out_size >= NPTS*COUT + NPTS*3) {
        copy_pts_kernel<<<(NPTS*3/4 + 255)/256, 256>>>(output_pts, out + (size_t)NPTS*COUT);
    }
}

// round 6
// speedup vs baseline: 3.8373x; 1.4205x over previous
#include <cuda_runtime.h>
#include <cuda_bf16.h>
#include <cuda_fp16.h>
#include <cstdint>

// Problem constants
#define NB   8
#define NN   8192
#define CIN  64
#define COUT 128
#define KNB  16
#define MM   16
#define NPTS (NB*NN)            // 65536
#define AGGK (CIN*MM)           // 1024

// -------- device scratch (no allocations allowed) --------
__device__ __half g_aggh[(size_t)NPTS * AGGK];   // 134 MB, [p][j], fp16
__device__ __half g_WpTh[(size_t)COUT * AGGK];   // weight^T [n][j], fp16, same j bijection
__device__ float  g_A1[32*3];
__device__ float  g_c1[32];

// j bijection: c = mt*16 + ih*8 + g  (mt<4, ih<2, g<8)
//              m = nt*8 + t4*2 + b   (nt<2, t4<4, b<2)
//              u = ((mt*2+ih)*2 + nt)*32 + g*4 + t4 ;  j = 2*u + b
// chosen so agg's mma C-fragments store as half2 at u = base + lane (coalesced).

// ============================================================
// PTX helpers (generic-target-safe: cp.async, mma.sync, ldmatrix)
// ============================================================
__device__ __forceinline__ uint32_t smem_u32(const void* p) {
    uint32_t a;
    asm("{ .reg .u64 t; cvta.to.shared.u64 t, %1; cvt.u32.u64 %0, t; }" : "=r"(a) : "l"(p));
    return a;
}
__device__ __forceinline__ uint32_t to_tf32u(float x) {
    uint32_t u;
    asm("cvt.rna.tf32.f32 %0, %1;" : "=r"(u) : "f"(x));
    return u;
}
#define CP_ASYNC16(dst, src) \
    asm volatile("cp.async.cg.shared.global [%0], [%1], 16;" :: "r"(dst), "l"(src) : "memory")
#define CP_COMMIT() asm volatile("cp.async.commit_group;" ::: "memory")
#define CP_WAIT1()  asm volatile("cp.async.wait_group 1;" ::: "memory")
#define CP_WAIT0()  asm volatile("cp.async.wait_group 0;" ::: "memory")

__device__ __forceinline__ void ldsm_x4(uint32_t& r0, uint32_t& r1, uint32_t& r2, uint32_t& r3,
                                        uint32_t addr) {
    asm volatile("ldmatrix.sync.aligned.m8n8.x4.shared.b16 {%0,%1,%2,%3}, [%4];"
                 : "=r"(r0), "=r"(r1), "=r"(r2), "=r"(r3) : "r"(addr));
}
__device__ __forceinline__ void mma_tf32(float c[4], const uint32_t a[4], const uint32_t b[2]) {
    asm volatile(
        "mma.sync.aligned.m16n8k8.row.col.f32.tf32.tf32.f32 "
        "{%0,%1,%2,%3}, {%4,%5,%6,%7}, {%8,%9}, {%0,%1,%2,%3};"
        : "+f"(c[0]), "+f"(c[1]), "+f"(c[2]), "+f"(c[3])
        : "r"(a[0]), "r"(a[1]), "r"(a[2]), "r"(a[3]), "r"(b[0]), "r"(b[1]));
}
__device__ __forceinline__ void mma_f16(float c[4], const uint32_t a[4], const uint32_t b[2]) {
    asm volatile(
        "mma.sync.aligned.m16n8k16.row.col.f32.f16.f16.f32 "
        "{%0,%1,%2,%3}, {%4,%5,%6,%7}, {%8,%9}, {%0,%1,%2,%3};"
        : "+f"(c[0]), "+f"(c[1]), "+f"(c[2]), "+f"(c[3])
        : "r"(a[0]), "r"(a[1]), "r"(a[2]), "r"(a[3]), "r"(b[0]), "r"(b[1]));
}

// ============================================================
// Prep 1: collapse MLP layer 1 (affine in rel coords).
// ============================================================
__global__ void prep_kernel(const float* __restrict__ l1_w,
                            const float* __restrict__ l1_b,
                            const float* __restrict__ centers)
{
    int o = threadIdx.x;
    if (o >= 32) return;
    float a0 = 0.f, a1 = 0.f, a2 = 0.f;
    float c = l1_b[o];
    #pragma unroll
    for (int m = 0; m < MM; m++) {
        float w0 = l1_w[o*48 + 0*16 + m];
        float w1 = l1_w[o*48 + 1*16 + m];
        float w2 = l1_w[o*48 + 2*16 + m];
        a0 += w0; a1 += w1; a2 += w2;
        c -= w0 * centers[0*16 + m];
        c -= w1 * centers[1*16 + m];
        c -= w2 * centers[2*16 + m];
    }
    g_A1[o*3+0] = a0; g_A1[o*3+1] = a1; g_A1[o*3+2] = a2;
    g_c1[o] = c;
}

// ============================================================
// Prep 2: weight[(c*16+m)*128 + n] -> g_WpTh[n*1024 + j(c,m)], fp16
// ============================================================
__global__ void permw_kernel(const float* __restrict__ weight)
{
    int e = blockIdx.x * blockDim.x + threadIdx.x;
    if (e >= AGGK * COUT) return;
    int n  = e & 127;
    int cm = e >> 7;
    int m  = cm & 15;
    int c  = cm >> 4;
    int gg = c & 7, ih = (c >> 3) & 1, mt = c >> 4;
    int nt = m >> 3, t4 = (m >> 1) & 3, b = m & 1;
    int u  = ((mt*2 + ih)*2 + nt)*32 + gg*4 + t4;
    g_WpTh[(size_t)n*AGGK + 2*u + b] = __float2half_rn(weight[e]);
}

// ============================================================
// Kernel A: gather + MLP + per-point agg via tf32 mma.sync.
// 1 warp = 2 points; fp16 coalesced stores via the j bijection.
// ============================================================
#define DP 17

__global__ __launch_bounds__(128)
void agg_kernel(const float* __restrict__ features,
                const float* __restrict__ input_pts,
                const float* __restrict__ output_pts,
                const int*   __restrict__ indices,
                const float* __restrict__ l2_w, const float* __restrict__ l2_b,
                const float* __restrict__ l3_w, const float* __restrict__ l3_b)
{
    __shared__ __align__(16) float sA1[96];
    __shared__ __align__(16) float sC1[32];
    __shared__ __align__(16) float sW2[16*32];
    __shared__ __align__(16) float sB2[16];
    __shared__ __align__(16) float sW3[16*16];
    __shared__ __align__(16) float sB3[16];
    __shared__ float sD[4][32][DP];
    __shared__ int   sI[4][2][KNB];

    const int tid = threadIdx.x;

    if (tid < 96)  sA1[tid] = g_A1[tid];
    if (tid < 32)  sC1[tid] = g_c1[tid];
    if (tid < 16)  { sB2[tid] = l2_b[tid]; sB3[tid] = l3_b[tid]; }
    for (int i = tid; i < 512; i += 128) sW2[i] = l2_w[i];
    for (int i = tid; i < 256; i += 128) sW3[i] = l3_w[i];
    __syncthreads();

    const int w     = tid >> 5;
    const int lane  = tid & 31;
    const int g     = lane >> 2;
    const int t4    = lane & 3;
    const int q     = lane >> 4;
    const int k     = lane & 15;
    const int pbase = blockIdx.x * 8 + w * 2;
    const int b     = pbase >> 13;
    const float* __restrict__ fb = features + (size_t)b * NN * CIN;

    // ---- phase 1: MLP, all 32 lanes (point q, neighbor k) ----
    {
        const int p   = pbase + q;
        const int idx = indices[p*KNB + k];
        sI[w][q][k] = idx;
        const float ox = output_pts[p*3+0];
        const float oy = output_pts[p*3+1];
        const float oz = output_pts[p*3+2];
        const float* ip = input_pts + (size_t)(b*NN + idx) * 3;
        const float rx = ip[0] - ox, ry = ip[1] - oy, rz = ip[2] - oz;

        float h1[32];
        #pragma unroll
        for (int o = 0; o < 32; o++) {
            float v = sC1[o] + sA1[o*3+0]*rx + sA1[o*3+1]*ry + sA1[o*3+2]*rz;
            h1[o] = fmaxf(v, 0.f);
        }
        float h2[16];
        #pragma unroll
        for (int o = 0; o < 16; o++) {
            float v = sB2[o];
            #pragma unroll
            for (int i4 = 0; i4 < 8; i4++) {
                float4 wv = *(const float4*)&sW2[o*32 + i4*4];
                v += wv.x*h1[i4*4+0] + wv.y*h1[i4*4+1]
                   + wv.z*h1[i4*4+2] + wv.w*h1[i4*4+3];
            }
            h2[o] = fmaxf(v, 0.f);
        }
        float* drow = sD[w][q*16 + k];
        #pragma unroll
        for (int o = 0; o < 16; o++) {
            float v = sB3[o];
            #pragma unroll
            for (int i4 = 0; i4 < 4; i4++) {
                float4 wv = *(const float4*)&sW3[o*16 + i4*4];
                v += wv.x*h2[i4*4+0] + wv.y*h2[i4*4+1]
                   + wv.z*h2[i4*4+2] + wv.w*h2[i4*4+3];
            }
            drow[o] = fmaxf(v, 0.f);
        }
    }
    __syncwarp();

    // ---- phase 3: per point, S = F^T(64x16) @ D(16x16) on tensor cores ----
    #pragma unroll
    for (int qq = 0; qq < 2; qq++) {
        float acc[4][2][4];
        #pragma unroll
        for (int mt = 0; mt < 4; mt++)
            #pragma unroll
            for (int nt = 0; nt < 2; nt++)
                #pragma unroll
                for (int i = 0; i < 4; i++) acc[mt][nt][i] = 0.f;

        #pragma unroll
        for (int kc = 0; kc < 2; kc++) {
            const float* r0 = fb + (size_t)sI[w][qq][kc*8 + t4]     * CIN;
            const float* r1 = fb + (size_t)sI[w][qq][kc*8 + t4 + 4] * CIN;

            uint32_t bfr[2][2];
            #pragma unroll
            for (int nt = 0; nt < 2; nt++) {
                bfr[nt][0] = to_tf32u(sD[w][qq*16 + kc*8 + t4    ][nt*8 + g]);
                bfr[nt][1] = to_tf32u(sD[w][qq*16 + kc*8 + t4 + 4][nt*8 + g]);
            }

            uint32_t a[4][4];
            #pragma unroll
            for (int mt = 0; mt < 4; mt++) {
                a[mt][0] = to_tf32u(r0[mt*16 + g    ]);
                a[mt][1] = to_tf32u(r0[mt*16 + g + 8]);
                a[mt][2] = to_tf32u(r1[mt*16 + g    ]);
                a[mt][3] = to_tf32u(r1[mt*16 + g + 8]);
            }

            #pragma unroll
            for (int mt = 0; mt < 4; mt++) {
                mma_tf32(acc[mt][0], a[mt], bfr[0]);
                mma_tf32(acc[mt][1], a[mt], bfr[1]);
            }
        }

        // coalesced fp16 stores: unit u = base + lane
        __half2* orow = (__half2*)(g_aggh + (size_t)(pbase + qq) * AGGK);
        #pragma unroll
        for (int mt = 0; mt < 4; mt++) {
            #pragma unroll
            for (int nt = 0; nt < 2; nt++) {
                const int u0 = ((mt*2 + 0)*2 + nt)*32 + lane;
                const int u1 = ((mt*2 + 1)*2 + nt)*32 + lane;
                orow[u0] = __floats2half2_rn(acc[mt][nt][0], acc[mt][nt][1]);
                orow[u1] = __floats2half2_rn(acc[mt][nt][2], acc[mt][nt][3]);
            }
        }
    }
}

// ============================================================
// Kernel B: fp16 mma.sync GEMM, fp32 accum.
// out[65536,128] = (g_aggh @ g_WpTh^T)/16 + bias
// 128x128 CTA tile, 8 warps (2x4, warp 64x32), K-chunk 64 halves,
// 3-stage cp.async pipeline, ldmatrix fragment loads, 1 sync/chunk.
// ============================================================
#define GBK    64                   // halves per K-chunk
#define HPITCH 72                   // halves pitch (144B) -> conflict-free LDSM
#define HTSZ   (128*HPITCH*2)       // 18432 B per tile per stage
#define GSTG   3
#define NCH    (AGGK/GBK)           // 16
#define GEMM_SMEM (GSTG*2*HTSZ + 512)

__global__ __launch_bounds__(256)
void gemm_mma_kernel(const float* __restrict__ bias, float* __restrict__ out)
{
    extern __shared__ __align__(16) char smem[];
    float* sbias = (float*)(smem + GSTG*2*HTSZ);

    const int tid  = threadIdx.x;
    const int lane = tid & 31;
    const int warp = tid >> 5;
    const int g    = lane >> 2;
    const int t4   = lane & 3;
    const int m0   = (warp >> 2) * 64;
    const int n0   = (warp & 3) * 32;
    const int p0   = blockIdx.x * 128;

    if (tid < COUT) sbias[tid] = bias[tid];

    const uint32_t smb = smem_u32(smem);

    // cp.async addressing: 1024 16B-atoms per tile / 256 thr = 4 each
    // atom a: row = a>>3, catom = a&7
    const __half* gA = g_aggh + (size_t)p0 * AGGK;
    const __half* gB = g_WpTh;

    auto load_chunk = [&](int kc, int st) {
        const uint32_t sa = smb + st*2*HTSZ;
        const uint32_t sb = sa + HTSZ;
        #pragma unroll
        for (int i = 0; i < 4; i++) {
            const int a   = tid + i*256;
            const int row = a >> 3;
            const int ca  = a & 7;
            const uint32_t doff = (uint32_t)(row*HPITCH + ca*8) * 2;
            CP_ASYNC16(sa + doff, gA + (size_t)row*AGGK + kc*GBK + ca*8);
            CP_ASYNC16(sb + doff, gB + (size_t)row*AGGK + kc*GBK + ca*8);
        }
    };

    // ldmatrix lane addressing
    const int a_r  = (lane & 7) + ((lane >> 3) & 1) * 8;   // row within 16
    const int a_ka = lane >> 4;                             // katom 0/1
    const int b_r  = (lane & 7) + (lane >> 4) * 8;          // row within 16
    const int b_ka = (lane >> 3) & 1;                       // katom 0/1

    float acc[4][4][4];
    #pragma unroll
    for (int mf = 0; mf < 4; mf++)
        #pragma unroll
        for (int nf = 0; nf < 4; nf++)
            #pragma unroll
            for (int i = 0; i < 4; i++) acc[mf][nf][i] = 0.f;

    load_chunk(0, 0); CP_COMMIT();
    load_chunk(1, 1); CP_COMMIT();

    for (int kc = 0; kc < NCH; kc++) {
        const int st = kc % GSTG;
        CP_WAIT1();
        __syncthreads();

        const uint32_t sa = smb + st*2*HTSZ;
        const uint32_t sb = sa + HTSZ;

        #pragma unroll
        for (int ks = 0; ks < 4; ks++) {          // 4 x k16 per 64-half chunk
            uint32_t a[4][4], bb[4][2];
            #pragma unroll
            for (int mf = 0; mf < 4; mf++) {
                uint32_t addr = sa + (uint32_t)((m0 + mf*16 + a_r)*HPITCH
                                + (ks*2 + a_ka)*8) * 2;
                ldsm_x4(a[mf][0], a[mf][1], a[mf][2], a[mf][3], addr);
            }
            #pragma unroll
            for (int np = 0; np < 2; np++) {
                uint32_t addr = sb + (uint32_t)((n0 + np*16 + b_r)*HPITCH
                                + (ks*2 + b_ka)*8) * 2;
                ldsm_x4(bb[np*2][0], bb[np*2][1], bb[np*2+1][0], bb[np*2+1][1], addr);
            }
            #pragma unroll
            for (int mf = 0; mf < 4; mf++)
                #pragma unroll
                for (int nf = 0; nf < 4; nf++)
                    mma_f16(acc[mf][nf], a[mf], bb[nf]);
        }

        if (kc + 2 < NCH) load_chunk(kc + 2, (kc + 2) % GSTG);
        CP_COMMIT();
    }

    // epilogue: /K + bias
    const float inv_k = 1.0f / (float)KNB;
    #pragma unroll
    for (int mf = 0; mf < 4; mf++) {
        const int row = p0 + m0 + mf*16 + g;
        #pragma unroll
        for (int nf = 0; nf < 4; nf++) {
            const int col = n0 + nf*8 + t4*2;
            const float b0 = sbias[col], b1 = sbias[col+1];
            float2 v0 = make_float2(acc[mf][nf][0]*inv_k + b0, acc[mf][nf][1]*inv_k + b1);
            float2 v1 = make_float2(acc[mf][nf][2]*inv_k + b0, acc[mf][nf][3]*inv_k + b1);
            *(float2*)(out + (size_t)row*COUT + col)     = v0;
            *(float2*)(out + (size_t)(row+8)*COUT + col) = v1;
        }
    }
}

// ============================================================
// Copy output_pts into the tail of the flattened tuple output.
// ============================================================
__global__ void copy_pts_kernel(const float* __restrict__ src, float* __restrict__ dst)
{
    int i = blockIdx.x * blockDim.x + threadIdx.x;
    const int n4 = (NPTS * 3) / 4;
    if (i < n4) ((float4*)dst)[i] = ((const float4*)src)[i];
}

// ============================================================
extern "C" void kernel_launch(void* const* d_in, const int* in_sizes, int n_in,
                              void* d_out, int out_size)
{
    const float* features   = (const float*)d_in[0];
    const float* input_pts  = (const float*)d_in[1];
    const float* output_pts = (const float*)d_in[2];
    const int*   indices    = (const int*)  d_in[3];
    const float* centers    = (const float*)d_in[4];
    const float* weight     = (const float*)d_in[5];
    const float* bias       = (const float*)d_in[6];
    const float* l1_w       = (const float*)d_in[7];
    const float* l1_b       = (const float*)d_in[8];
    const float* l2_w       = (const float*)d_in[9];
    const float* l2_b       = (const float*)d_in[10];
    const float* l3_w       = (const float*)d_in[11];
    const float* l3_b       = (const float*)d_in[12];

    float* out = (float*)d_out;

    cudaFuncSetAttribute(gemm_mma_kernel,
                         cudaFuncAttributeMaxDynamicSharedMemorySize, GEMM_SMEM);

    prep_kernel<<<1, 32>>>(l1_w, l1_b, centers);
    permw_kernel<<<(AGGK*COUT + 255)/256, 256>>>(weight);
    agg_kernel<<<NPTS/8, 128>>>(features, input_pts, output_pts, indices,
                                l2_w, l2_b, l3_w, l3_b);
    gemm_mma_kernel<<<NPTS/128, 256, GEMM_SMEM>>>(bias, out);

    if (out_size >= NPTS*COUT + NPTS*3) {
        copy_pts_kernel<<<(NPTS*3/4 + 255)/256, 256>>>(output_pts, out + (size_t)NPTS*COUT);
    }
}